// round 8
// baseline (speedup 1.0000x reference)
#include <cuda_runtime.h>
#include <math.h>

#define B_ 32
#define S_ 512
#define T_ 128
#define H_ 1024
#define H3 3072
#define F2 4096
#define FF 2048
#define V_ 128
#define GRID 144
#define NTHR 256

__device__ float g_Xs[B_*S_*1024];
__device__ float g_Xt[B_*T_*1024];
__device__ float g_enc[B_*S_*512];
__device__ float g_tem[B_*T_*512];
__device__ float g_gie[(size_t)B_*S_*H3];
__device__ float g_gid[(size_t)B_*T_*H3];
__device__ float g_es[(size_t)B_*S_*H_];
__device__ float g_av[(size_t)B_*S_*H_];
__device__ float g_h[B_*H_];
__device__ float g_hd[B_*H_];
__device__ float g_ctA[B_*H_], g_ctB[B_*H_];
__device__ float g_ghp[6*B_*H3];
__device__ float g_cip[6*B_*H3];
__device__ float g_y1p[4*B_*F2];
__device__ float g_y2p[16*B_*FF];
__device__ float g_qp[4*B_*H_];
__device__ float g_sp[8*B_*V_];
__device__ float g_att[B_*S_];
__device__ float g_st[512];
__device__ float g_xc[B_*1536];
__device__ unsigned g_cnt = 0, g_gen = 0;

__device__ __forceinline__ void gsync() {
    __syncthreads();
    if (threadIdx.x == 0) {
        __threadfence();
        unsigned gen = atomicAdd(&g_gen, 0u);
        if (atomicAdd(&g_cnt, 1u) == GRID - 1u) {
            g_cnt = 0;
            __threadfence();
            atomicAdd(&g_gen, 1u);
        } else {
            while (atomicAdd(&g_gen, 0u) == gen) __nanosleep(64);
        }
        __threadfence();
    }
    __syncthreads();
}

// C[b, n0..n0+127] partial over k in [k0,k0+klen). 256 thr, 4b x 4n microtile.
// A: direct A0(+A1) stride astr, or reduce P slabs AP (+bias ab, relu rl), row width apN.
__device__ __noinline__ void sgemm(float* SP,
    const float* A0, const float* A1, int astr,
    const float* AP, long sstr, int P, const float* ab, int rl, int apN,
    const float* W, int ldw, int n0, int k0, int klen, float* C, int cN)
{
    float* As = SP;            // [32k][36]
    float* Ws = SP + 1152;     // [32k][132]
    int tid = threadIdx.x, bq = tid >> 5, nq = tid & 31;
    float ac[4][4] = {};
    for (int kk = k0; kk < k0 + klen; kk += 32) {
        __syncthreads();
        {
            int b = tid >> 3, kq = tid & 7, ko = kk + kq * 4;
            float4 v;
            if (AP) {
                v = make_float4(0.f, 0.f, 0.f, 0.f);
                for (int p = 0; p < P; p++) {
                    float4 u = *(const float4*)&AP[(long)p * sstr + (long)b * apN + ko];
                    v.x += u.x; v.y += u.y; v.z += u.z; v.w += u.w;
                }
                if (ab) { float4 u = *(const float4*)&ab[ko]; v.x += u.x; v.y += u.y; v.z += u.z; v.w += u.w; }
                if (rl) { v.x = fmaxf(v.x, 0.f); v.y = fmaxf(v.y, 0.f); v.z = fmaxf(v.z, 0.f); v.w = fmaxf(v.w, 0.f); }
            } else {
                v = *(const float4*)&A0[(long)b * astr + ko];
                if (A1) { float4 u = *(const float4*)&A1[(long)b * astr + ko]; v.x += u.x; v.y += u.y; v.z += u.z; v.w += u.w; }
            }
            As[(kq*4+0)*36+b] = v.x; As[(kq*4+1)*36+b] = v.y;
            As[(kq*4+2)*36+b] = v.z; As[(kq*4+3)*36+b] = v.w;
        }
#pragma unroll
        for (int it = 0; it < 4; it++) {
            int r = nq + it * 32;
            float4 v = *(const float4*)&W[(long)(n0 + r) * ldw + kk + bq * 4];
            Ws[(bq*4+0)*132+r] = v.x; Ws[(bq*4+1)*132+r] = v.y;
            Ws[(bq*4+2)*132+r] = v.z; Ws[(bq*4+3)*132+r] = v.w;
        }
        __syncthreads();
#pragma unroll
        for (int k = 0; k < 32; k++) {
            float4 a = *(const float4*)&As[k*36 + bq*4];
            float4 w = *(const float4*)&Ws[k*132 + nq*4];
            float avv[4] = {a.x, a.y, a.z, a.w}, wv[4] = {w.x, w.y, w.z, w.w};
#pragma unroll
            for (int i = 0; i < 4; i++)
#pragma unroll
                for (int j = 0; j < 4; j++) ac[i][j] = fmaf(avv[i], wv[j], ac[i][j]);
        }
    }
#pragma unroll
    for (int i = 0; i < 4; i++)
        *(float4*)&C[(long)(bq*4+i)*cN + n0 + nq*4] = *(float4*)ac[i];
}

__global__ void gather_k(const int* __restrict__ ch, const int* __restrict__ lg,
                         const float* __restrict__ ce, const float* __restrict__ le,
                         float* __restrict__ X, int ntok) {
    long i = (long)blockIdx.x * 256 + threadIdx.x;
    if (i >= (long)ntok * 1024) return;
    int tok = (int)(i >> 10), c = (int)(i & 1023);
    X[i] = (c < 512) ? ce[ch[tok] * 512 + c] : le[(lg ? lg[tok] : 4) * 512 + (c - 512)];
}

__global__ void startemb_k(const float* __restrict__ ce, const float* __restrict__ le,
                           const float* __restrict__ fcW, const float* __restrict__ fcb,
                           float* __restrict__ o) {
    int g = blockIdx.x * 8 + (threadIdx.x >> 5), l = threadIdx.x & 31;
    float a = 0.f;
    for (int k = l; k < 1024; k += 32)
        a += ((k < 512) ? ce[512 + k] : le[2048 + (k - 512)]) * fcW[g * 1024 + k];
#pragma unroll
    for (int s = 16; s; s >>= 1) a += __shfl_down_sync(~0u, a, s);
    if (!l) o[g] = a + fcb[g];
}

// big GEMM for precompute: C[M,N] = A[M,K]@W[N,K]^T (+bias)(+=C)
__global__ void gemm_nt(const float* __restrict__ A, int lda,
                        const float* __restrict__ W, int ldw,
                        const float* __restrict__ bias,
                        float* __restrict__ C, int ldc, int K, int accf) {
    __shared__ float As[8][128], Ws[8][128];
    int bm = blockIdx.y * 128, bn = blockIdx.x * 128, tid = threadIdx.x;
    int lr = tid >> 1, lc = (tid & 1) * 4, tx = tid & 15, ty = tid >> 4;
    float acc[8][8] = {};
    for (int k0 = 0; k0 < K; k0 += 8) {
        float4 a = *(const float4*)&A[(long)(bm + lr) * lda + k0 + lc];
        float4 w = *(const float4*)&W[(long)(bn + lr) * ldw + k0 + lc];
        As[lc][lr] = a.x; As[lc+1][lr] = a.y; As[lc+2][lr] = a.z; As[lc+3][lr] = a.w;
        Ws[lc][lr] = w.x; Ws[lc+1][lr] = w.y; Ws[lc+2][lr] = w.z; Ws[lc+3][lr] = w.w;
        __syncthreads();
#pragma unroll
        for (int k = 0; k < 8; k++) {
            float avv[8], bv[8];
            *(float4*)avv = *(const float4*)&As[k][ty*8]; *(float4*)(avv+4) = *(const float4*)&As[k][ty*8+4];
            *(float4*)bv = *(const float4*)&Ws[k][tx*8]; *(float4*)(bv+4) = *(const float4*)&Ws[k][tx*8+4];
#pragma unroll
            for (int i = 0; i < 8; i++)
#pragma unroll
                for (int j = 0; j < 8; j++) acc[i][j] = fmaf(avv[i], bv[j], acc[i][j]);
        }
        __syncthreads();
    }
#pragma unroll
    for (int i = 0; i < 8; i++) {
        long row = bm + ty * 8 + i;
#pragma unroll
        for (int j = 0; j < 8; j += 4) {
            int col = bn + tx * 8 + j;
            float4 v = make_float4(acc[i][j], acc[i][j+1], acc[i][j+2], acc[i][j+3]);
            if (bias) { v.x += bias[col]; v.y += bias[col+1]; v.z += bias[col+2]; v.w += bias[col+3]; }
            float4* cp = (float4*)&C[row * ldc + col];
            if (accf) { float4 o = *cp; v.x += o.x; v.y += o.y; v.z += o.z; v.w += o.w; }
            *cp = v;
        }
    }
}

__global__ void __launch_bounds__(NTHR, 1) enc_pk(const float* __restrict__ Wh,
                                                  const float* __restrict__ bh) {
    __shared__ float SP[5376];
    int bid = blockIdx.x, tid = threadIdx.x;
    for (int i = bid * NTHR + tid; i < B_ * H_; i += GRID * NTHR) g_h[i] = 0.f;
    gsync();
    const int kb[7] = {0, 192, 384, 544, 704, 864, 1024};
    for (int t = 0; t < S_; t++) {
        int nt = bid / 6, ks = bid % 6;
        sgemm(SP, g_h, 0, H_, 0, 0, 0, 0, 0, 0, Wh, H_, nt * 128, kb[ks], kb[ks+1] - kb[ks],
              g_ghp + (long)ks * B_ * H3, H3);
        gsync();
        for (int i = bid * NTHR + tid; i < B_ * H_; i += GRID * NTHR) {
            int b = i >> 10, j = i & 1023;
            const float* gi = &g_gie[((size_t)(b * S_ + t)) * H3];
            float ir = gi[j], iz = gi[j + H_], in = gi[j + 2*H_];
            float hr = bh[j], hz = bh[j + H_], hn = bh[j + 2*H_];
            for (int p = 0; p < 6; p++) {
                const float* gp = &g_ghp[(long)p * B_ * H3 + (long)b * H3];
                hr += gp[j]; hz += gp[j + H_]; hn += gp[j + 2*H_];
            }
            float ho = g_h[i];
            float r = 1.f / (1.f + expf(-(ir + hr)));
            float z = 1.f / (1.f + expf(-(iz + hz)));
            float n = tanhf(in + r * hn);
            float hv = (1.f - z) * n + z * ho;
            g_h[i] = hv;
            g_es[((size_t)(b * S_ + t)) * H_ + j] = hv;
        }
        gsync();
    }
}

__global__ void __launch_bounds__(NTHR, 1) dec_pk(
    const float* __restrict__ Wi, const float* __restrict__ Wh,
    const float* __restrict__ bi, const float* __restrict__ bh,
    const float* __restrict__ Wq, const float* __restrict__ W1, const float* __restrict__ b1,
    const float* __restrict__ W2, const float* __restrict__ b2, const float* __restrict__ W3,
    float* __restrict__ out) {
    __shared__ float SP[5376];
    int bid = blockIdx.x, tid = threadIdx.x;
    // init: xcat, gi0 partials, h0
    for (int i = bid * NTHR + tid; i < B_ * 1536; i += GRID * NTHR) {
        int b = i / 1536, k = i % 1536;
        float v = (k < 512) ? g_st[k] : g_es[((size_t)(b * S_ + S_ - 1)) * H_ + k - 512];
        if (k >= 512) g_ctA[b * H_ + k - 512] = v;
        g_xc[i] = v;
    }
    gsync();
    { int nt = bid / 6, ks = bid % 6;
      sgemm(SP, g_xc, 0, 1536, 0, 0, 0, 0, 0, 0, Wi, 1536, nt * 128, ks * 256, 256,
            g_cip + (long)ks * B_ * H3, H3); }
    gsync();
    for (int i = bid * NTHR + tid; i < B_ * H_; i += GRID * NTHR) {
        int b = i >> 10, j = i & 1023;
        float ir = bi[j], iz = bi[j + H_], in = bi[j + 2*H_];
        for (int p = 0; p < 6; p++) {
            const float* gp = &g_cip[(long)p * B_ * H3 + (long)b * H3];
            ir += gp[j]; iz += gp[j + H_]; in += gp[j + 2*H_];
        }
        float hr = bh[j], hz = bh[j + H_], hn = bh[j + 2*H_];
        float r = 1.f / (1.f + expf(-(ir + hr)));
        float z = 1.f / (1.f + expf(-(iz + hz)));
        float n = tanhf(in + r * hn);
        g_hd[i] = (1.f - z) * n;
    }
    gsync();
    for (int t = 0; t < T_; t++) {
        const float* cp = (t & 1) ? g_ctB : g_ctA;
        float* cn = (t & 1) ? g_ctA : g_ctB;
        for (int it = bid; it < 256; it += GRID) {           // S1
            if (it < 128) { int nt = it >> 2, ks = it & 3;
                sgemm(SP, g_hd, cp, H_, 0,0,0,0,0,0, W1, H_, nt*128, ks*256, 256, g_y1p + (long)ks*B_*F2, F2); }
            else if (it < 160) { int i2 = it - 128, nt = i2 >> 2, ks = i2 & 3;
                sgemm(SP, g_hd, 0, H_, 0,0,0,0,0,0, Wq, H_, nt*128, ks*256, 256, g_qp + (long)ks*B_*H_, H_); }
            else { int i2 = it - 160, nt = i2 >> 2, ks = i2 & 3;
                sgemm(SP, g_hd, 0, H_, 0,0,0,0,0,0, Wh, H_, nt*128, ks*256, 256, g_ghp + (long)ks*B_*H3, H3); }
        }
        gsync();
        for (int it = bid; it < 288; it += GRID) {           // S2
            if (it < 256) { int nt = it >> 4, ks = it & 15;
                sgemm(SP, 0,0,0, g_y1p, (long)B_*F2, 4, b1, 1, F2, W2, F2, nt*128, ks*256, 256,
                      g_y2p + (long)ks*B_*FF, FF); }
            else {
                int b = it - 256;
                __syncthreads();
                for (int i = tid; i < H_; i += NTHR) {
                    float s = 0.f;
                    for (int p = 0; p < 4; p++) s += g_qp[(long)p*B_*H_ + b*H_ + i];
                    SP[i] = s;
                }
                __syncthreads();
                int w = tid >> 5, l = tid & 31;
                for (int s = w; s < S_; s += 8) {
                    const float* e = &g_es[((size_t)(b * S_ + s)) * H_];
                    float a = 0.f;
#pragma unroll
                    for (int m = 0; m < 8; m++) {
                        float4 ev = *(const float4*)&e[m*128 + l*4];
                        float4 qv = *(const float4*)&SP[m*128 + l*4];
                        a += ev.x*qv.x + ev.y*qv.y + ev.z*qv.z + ev.w*qv.w;
                    }
#pragma unroll
                    for (int o = 16; o; o >>= 1) a += __shfl_down_sync(~0u, a, o);
                    if (!l) g_att[b * S_ + s] = a;
                }
                __syncthreads();
            }
        }
        gsync();
        for (int it = bid; it < 136; it += GRID) {           // S3
            if (it < 128) {
                int b = it >> 2, hq = it & 3;
                float* red = SP + 512;
                __syncthreads();
                float v0 = g_att[b*S_ + tid], v1 = g_att[b*S_ + 256 + tid];
                red[tid] = fmaxf(v0, v1); __syncthreads();
                for (int s = 128; s; s >>= 1) { if (tid < s) red[tid] = fmaxf(red[tid], red[tid+s]); __syncthreads(); }
                float mx = red[0]; __syncthreads();
                float e0 = expf(v0 - mx), e1 = expf(v1 - mx);
                red[tid] = e0 + e1; __syncthreads();
                for (int s = 128; s; s >>= 1) { if (tid < s) red[tid] += red[tid+s]; __syncthreads(); }
                float inv = 1.f / red[0]; __syncthreads();
                SP[tid] = e0 * inv; SP[tid + 256] = e1 * inv;
                __syncthreads();
                int hc = hq * 256 + tid;
                const float* a = &g_av[((size_t)b * S_) * H_ + hc];
                float acc = 0.f;
#pragma unroll 8
                for (int s = 0; s < S_; s++) acc += SP[s] * a[(long)s * H_];
                cn[b * H_ + hc] = acc;
                __syncthreads();
            } else { int ks = it - 128;
                sgemm(SP, 0,0,0, g_y2p, (long)B_*FF, 16, b2, 1, FF, W3, FF, 0, ks*256, 256,
                      g_sp + (long)ks*B_*V_, V_); }
        }
        gsync();
        for (int it = bid; it < 96; it += GRID) {            // S4
            int nt = it >> 2, ks = it & 3;
            sgemm(SP, cn, 0, H_, 0,0,0,0,0,0, Wi + 512, 1536, nt*128, ks*256, 256,
                  g_cip + (long)ks*B_*H3, H3);
        }
        gsync();
        for (int i = bid * NTHR + tid; i < B_ * H_; i += GRID * NTHR) {   // S5 gates
            int b = i >> 10, j = i & 1023;
            const float* gi = &g_gid[((size_t)(b * T_ + t)) * H3];
            float ir = gi[j], iz = gi[j + H_], in = gi[j + 2*H_];
            for (int p = 0; p < 4; p++) {
                const float* gp = &g_cip[(long)p*B_*H3 + (long)b*H3];
                ir += gp[j]; iz += gp[j + H_]; in += gp[j + 2*H_];
            }
            float hr = bh[j], hz = bh[j + H_], hn = bh[j + 2*H_];
            for (int p = 0; p < 4; p++) {
                const float* gp = &g_ghp[(long)p*B_*H3 + (long)b*H3];
                hr += gp[j]; hz += gp[j + H_]; hn += gp[j + 2*H_];
            }
            float ho = g_hd[i];
            float r = 1.f / (1.f + expf(-(ir + hr)));
            float z = 1.f / (1.f + expf(-(iz + hz)));
            float n = tanhf(in + r * hn);
            g_hd[i] = (1.f - z) * n + z * ho;
        }
        for (int i = bid * NTHR + tid; i < B_ * V_; i += GRID * NTHR) {   // scores out
            int b = i >> 7, v = i & 127;
            float s = 0.f;
            for (int p = 0; p < 8; p++) s += g_sp[p*B_*V_ + b*V_ + v];
            out[((size_t)(b * T_ + t)) * V_ + v] = s;
        }
        gsync();
    }
}

static float* sym(const void* s) { void* p = 0; cudaGetSymbolAddress(&p, s); return (float*)p; }

extern "C" void kernel_launch(void* const* d_in, const int*, int, void* d_out, int) {
    const int* sc = (const int*)d_in[0];  const int* sl = (const int*)d_in[1];
    const int* tc = (const int*)d_in[2];
    const float* ce = (const float*)d_in[3];  const float* le = (const float*)d_in[4];
    const float* fcW = (const float*)d_in[5]; const float* fcb = (const float*)d_in[6];
    const float* eWi = (const float*)d_in[7]; const float* eWh = (const float*)d_in[8];
    const float* ebi = (const float*)d_in[9]; const float* ebh = (const float*)d_in[10];
    const float* dWi = (const float*)d_in[11]; const float* dWh = (const float*)d_in[12];
    const float* dbi = (const float*)d_in[13]; const float* dbh = (const float*)d_in[14];
    const float* Wq = (const float*)d_in[15]; const float* Wk = (const float*)d_in[16];
    const float* Wcs = (const float*)d_in[17];
    const float* W1 = (const float*)d_in[18]; const float* b1 = (const float*)d_in[19];
    const float* W2 = (const float*)d_in[20]; const float* b2 = (const float*)d_in[21];
    const float* W3 = (const float*)d_in[22];
    float* out = (float*)d_out;
    float *Xs = sym(g_Xs), *Xt = sym(g_Xt), *enc = sym(g_enc), *tem = sym(g_tem),
          *gie = sym(g_gie), *gid = sym(g_gid), *es = sym(g_es), *av = sym(g_av), *st = sym(g_st);

    gather_k<<<(B_*S_*1024)/256, 256>>>(sc, sl, ce, le, Xs, B_*S_);
    gather_k<<<(B_*T_*1024)/256, 256>>>(tc, 0, ce, le, Xt, B_*T_);
    gemm_nt<<<dim3(4, B_*S_/128), 256>>>(Xs, 1024, fcW, 1024, fcb, enc, 512, 1024, 0);
    gemm_nt<<<dim3(4, B_*T_/128), 256>>>(Xt, 1024, fcW, 1024, fcb, tem, 512, 1024, 0);
    gemm_nt<<<dim3(H3/128, B_*S_/128), 256>>>(enc, 512, eWi, 512, ebi, gie, H3, 512, 0);
    gemm_nt<<<dim3(H3/128, B_*T_/128), 256>>>(tem, 512, dWi, 1536, dbi, gid, H3, 512, 0);
    gemm_nt<<<dim3(H_/128, B_*S_/128), 256>>>(enc, 512, Wcs, 512, 0, av, H_, 512, 0);
    startemb_k<<<64, 256>>>(ce, le, fcW, fcb, st);
    enc_pk<<<GRID, NTHR>>>(eWh, ebh);
    gemm_nt<<<dim3(H_/128, B_*S_/128), 256>>>(es, H_, Wk, H_, 0, av, H_, 1024, 1);
    dec_pk<<<GRID, NTHR>>>(dWi, dWh, dbi, dbh, Wq, W1, b1, W2, b2, W3, out);
}